// round 13
// baseline (speedup 1.0000x reference)
#include <cuda_runtime.h>

#define NV   2000000
#define NC   2000
#define NE   16000
#define NREP 16        // replicas per cluster, padded to 32B stride
#define GRID 296       // 2 CTAs/SM x 148 SMs: all blocks co-resident
#define TPB  256

// Scratch (no cudaMalloc allowed).
// Replica r of cluster c at float4 index c*32 + r*2; .x/.y/.z hold f0/f1/f2.
__device__ float4       g_rsum[NC * NREP * 2];
__device__ float        g_f3[NC];           // f3 sums (smem-aggregated)
__device__ unsigned int g_icnt[NC];         // counts  (smem-aggregated)
// Monotonic grid-barrier counters (never reset; grow by GRID per launch).
__device__ unsigned int g_bar0, g_bar1;

__device__ __forceinline__ void red_f(float* a, float v) {
    asm volatile("red.global.add.f32 [%0], %1;" :: "l"(a), "f"(v) : "memory");
}
__device__ __forceinline__ void red_u32(unsigned int* a, unsigned int v) {
    asm volatile("red.global.add.u32 [%0], %1;" :: "l"(a), "r"(v) : "memory");
}
__device__ __forceinline__ unsigned long long pack2(float a, float b) {
    unsigned long long r;
    asm("mov.b64 %0, {%1, %2};" : "=l"(r) : "f"(a), "f"(b));
    return r;
}
__device__ __forceinline__ void unpack2(unsigned long long v, float& a, float& b) {
    asm("mov.b64 {%0, %1}, %2;" : "=f"(a), "=f"(b) : "l"(v));
}
__device__ __forceinline__ void ffma2(unsigned long long& d,
                                      unsigned long long a, unsigned long long b) {
    asm("fma.rn.f32x2 %0, %1, %2, %0;" : "+l"(d) : "l"(a), "l"(b));
}

// Software grid barrier: monotonic counter, wrap-free across graph replays.
// All GRID blocks co-resident (2 CTAs/SM @ 80KB smem), so spinning is safe.
__device__ __forceinline__ void grid_barrier(unsigned int* ctr) {
    __syncthreads();
    if (threadIdx.x == 0) {
        __threadfence();
        unsigned int t = atomicAdd(ctr, 1u);
        unsigned int target = (t / GRID + 1u) * GRID;
        unsigned int v;
        do {
            asm volatile("ld.acquire.gpu.u32 %0, [%1];" : "=r"(v) : "l"(ctr));
        } while (v < target);
        __threadfence();
    }
    __syncthreads();
}

// ---------------------------------------------------------------------------
// ONE fused kernel, 296 x 256 (R10 shape).
// Phase 1 splits atomic work across BOTH pipes:
//   f0,f1,f2 -> 3 scalar red.f32 lanes/voxel to padded L2 replicas (LTS pipe)
//   f3,count -> smem histograms (ATOMS pipe, runs concurrently), flushed once.
// smem floats: W2 [0,8192) | h [8192,16384) | misc [16384,20480) (16KB)
// ---------------------------------------------------------------------------
__global__ __launch_bounds__(TPB) void k_fused(const float* __restrict__ data,
                                               const int*   __restrict__ cid,
                                               const int*   __restrict__ eidx,
                                               const float* __restrict__ W1,
                                               const float* __restrict__ b1,
                                               const float* __restrict__ W2,
                                               const float* __restrict__ b2,
                                               float*       __restrict__ out) {
    extern __shared__ float sm[];
    float* s_W2   = sm;                      // 8192 floats [128][64]
    float* s_h    = sm + 8192;               // 8192 floats [128][64] k-major
    float* s_misc = sm + 16384;              // 4096 floats

    const int t   = threadIdx.x;
    const int bid = blockIdx.x;

    // ---- Phase 0: zero accumulators; preload W2; zero smem hists ----
    for (int i = bid * TPB + t; i < NC * NREP * 2; i += GRID * TPB)
        g_rsum[i] = make_float4(0.f, 0.f, 0.f, 0.f);
    for (int i = bid * TPB + t; i < NC; i += GRID * TPB) {
        g_icnt[i] = 0u;
        g_f3[i]   = 0.f;
    }
    for (int i = t; i < 8192 / 4; i += TPB)
        ((float4*)s_W2)[i] = ((const float4*)W2)[i];
    float*        s_f3  = s_misc;                       // 8KB float hist
    unsigned int* s_cnt = (unsigned int*)(s_misc + NC); // 8KB count hist
    for (int i = t; i < NC; i += TPB) { s_f3[i] = 0.f; s_cnt[i] = 0u; }

    grid_barrier(&g_bar0);

    // ---- Phase 1: segment sum, dual-pipe ----
    {
        const int rep2 = ((bid * 8 + (t >> 5)) & (NREP - 1)) * 2;
        const int NG = NV / 4;
        const int stride = GRID * TPB;
#pragma unroll 2
        for (int g = bid * TPB + t; g < NG; g += stride) {
            const float4* p = (const float4*)data + (size_t)g * 5;
            float4 q0 = __ldcs(p + 0);
            float4 q1 = __ldcs(p + 1);
            float4 q2 = __ldcs(p + 2);
            float4 q3 = __ldcs(p + 3);
            float4 q4 = __ldcs(p + 4);
            int4 c = __ldcs((const int4*)cid + g);

            // voxel layout: [d f0 f1 f2 f3] x4 -> features are cols 1..4
            float* rx = (float*)&g_rsum[c.x * (NREP * 2) + rep2];
            float* ry = (float*)&g_rsum[c.y * (NREP * 2) + rep2];
            float* rz = (float*)&g_rsum[c.z * (NREP * 2) + rep2];
            float* rw = (float*)&g_rsum[c.w * (NREP * 2) + rep2];
            // f0,f1,f2 via REDG (3 lanes/voxel)
            red_f(rx + 0, q0.y); red_f(rx + 1, q0.z); red_f(rx + 2, q0.w);
            red_f(ry + 0, q1.z); red_f(ry + 1, q1.w); red_f(ry + 2, q2.x);
            red_f(rz + 0, q2.w); red_f(rz + 1, q3.x); red_f(rz + 2, q3.y);
            red_f(rw + 0, q4.x); red_f(rw + 1, q4.y); red_f(rw + 2, q4.z);
            // f3 + count via smem ATOMS (concurrent pipe)
            atomicAdd(&s_f3[c.x], q1.x);  atomicAdd(&s_cnt[c.x], 1u);
            atomicAdd(&s_f3[c.y], q2.y);  atomicAdd(&s_cnt[c.y], 1u);
            atomicAdd(&s_f3[c.z], q3.z);  atomicAdd(&s_cnt[c.z], 1u);
            atomicAdd(&s_f3[c.w], q4.w);  atomicAdd(&s_cnt[c.w], 1u);
        }
        __syncthreads();
        for (int i = t; i < NC; i += TPB) {
            float v = s_f3[i];
            if (v != 0.f) red_f(&g_f3[i], v);
            unsigned int u = s_cnt[i];
            if (u) red_u32(&g_icnt[i], u);
        }
    }

    grid_barrier(&g_bar1);

    // ---- Phase 2: edge MLP on blocks 0..249 (64 edges each) ----
    if (bid >= NE / 64) return;

    float* s_W1   = s_misc;          // 512 floats [4][128]  (hists are dead)
    float* s_b1   = s_misc + 512;    // 128
    float* s_b2   = s_misc + 640;    // 64
    float* s_pool = s_misc + 704;    // 320 floats [64][5]

    __syncthreads();
    if (t < 128) ((float4*)s_W1)[t] = ((const float4*)W1)[t];
    if (t < 128) s_b1[t] = b1[t];
    if (t < 64)  s_b2[t] = b2[t];

    const int base = bid * 64;

    // Gather: 4 threads/edge, each sums 4 padded replicas of both endpoints
    // (8 pipelined LDG.128 from warm L2), 2-step shfl reduce; f3/cnt direct.
    {
        int q = t & 3;
        int e = t >> 2;
        int eg = base + e;
        int a = __ldg(eidx + eg);
        int b = __ldg(eidx + NE + eg);

        const float4* ra = g_rsum + a * (NREP * 2) + q * 8;
        const float4* rb = g_rsum + b * (NREP * 2) + q * 8;
        float4 s = make_float4(0.f, 0.f, 0.f, 0.f);
#pragma unroll
        for (int r = 0; r < 4; r++) {
            float4 va = __ldg(ra + r * 2);
            float4 vb = __ldg(rb + r * 2);
            s.x += va.x + vb.x;
            s.y += va.y + vb.y;
            s.z += va.z + vb.z;
        }
#pragma unroll
        for (int off = 2; off > 0; off >>= 1) {
            s.x += __shfl_down_sync(0xffffffff, s.x, off);
            s.y += __shfl_down_sync(0xffffffff, s.y, off);
            s.z += __shfl_down_sync(0xffffffff, s.z, off);
        }
        if (q == 0) {
            float f3  = __ldg(g_f3 + a) + __ldg(g_f3 + b);
            float cnt = (float)(__ldg(g_icnt + a) + __ldg(g_icnt + b));
            float inv = 1.f / fmaxf(cnt, 1.f);
            s_pool[e * 5 + 0] = s.x * inv;
            s_pool[e * 5 + 1] = s.y * inv;
            s_pool[e * 5 + 2] = s.z * inv;
            s_pool[e * 5 + 3] = f3  * inv;
        }
    }
    __syncthreads();

    // Phase A: e = t&63, k-group kq = (t>>6)*32.
    {
        int e  = t & 63;
        int kq = (t >> 6) * 32;
        float p0 = s_pool[e * 5 + 0];
        float p1 = s_pool[e * 5 + 1];
        float p2 = s_pool[e * 5 + 2];
        float p3 = s_pool[e * 5 + 3];
#pragma unroll 4
        for (int j = 0; j < 32; j++) {
            int k = kq + j;
            float h = s_b1[k]
                    + p0 * s_W1[0 * 128 + k]
                    + p1 * s_W1[1 * 128 + k]
                    + p2 * s_W1[2 * 128 + k]
                    + p3 * s_W1[3 * 128 + k];
            s_h[k * 64 + e] = fmaxf(h, 0.f);
        }
    }
    __syncthreads();

    // Phase B: 4 edges x 4 outs per thread, packed f32x2 accumulators.
    const int tx = t & 15;
    const int ty = t >> 4;
    unsigned long long acc[4][2];
#pragma unroll
    for (int i = 0; i < 4; i++) { acc[i][0] = 0ull; acc[i][1] = 0ull; }

    const float4* hf4 = (const float4*)s_h;    // [128][16]
    const float4* wf4 = (const float4*)s_W2;   // [128][16]
#pragma unroll 4
    for (int k = 0; k < 128; k++) {
        float4 w = wf4[k * 16 + tx];           // conflict-free
        float4 h = hf4[k * 16 + ty];           // broadcast
        unsigned long long w01 = pack2(w.x, w.y);
        unsigned long long w23 = pack2(w.z, w.w);
        float hv[4] = {h.x, h.y, h.z, h.w};
#pragma unroll
        for (int i = 0; i < 4; i++) {
            unsigned long long hh = pack2(hv[i], hv[i]);
            ffma2(acc[i][0], hh, w01);
            ffma2(acc[i][1], hh, w23);
        }
    }

    float c0 = s_b2[tx * 4 + 0];
    float c1 = s_b2[tx * 4 + 1];
    float c2 = s_b2[tx * 4 + 2];
    float c3 = s_b2[tx * 4 + 3];
#pragma unroll
    for (int i = 0; i < 4; i++) {
        int e = base + ty * 4 + i;
        float a0, a1, a2, a3;
        unpack2(acc[i][0], a0, a1);
        unpack2(acc[i][1], a2, a3);
        float4 o = make_float4(a0 + c0, a1 + c1, a2 + c2, a3 + c3);
        ((float4*)out)[e * 16 + tx] = o;
    }
}

// ---------------------------------------------------------------------------
// Launch: ONE kernel node (graph-capturable)
// ---------------------------------------------------------------------------
extern "C" void kernel_launch(void* const* d_in, const int* in_sizes, int n_in,
                              void* d_out, int out_size) {
    const float* data = (const float*)d_in[0];
    const int*   cid  = (const int*)  d_in[1];
    const int*   eidx = (const int*)  d_in[2];
    const float* W1   = (const float*)d_in[3];
    const float* b1   = (const float*)d_in[4];
    const float* W2   = (const float*)d_in[5];
    const float* b2   = (const float*)d_in[6];
    float*       out  = (float*)d_out;

    cudaFuncSetAttribute(k_fused, cudaFuncAttributeMaxDynamicSharedMemorySize, 81920);

    k_fused<<<GRID, TPB, 81920>>>(data, cid, eidx, W1, b1, W2, b2, out);
}

// round 14
// speedup vs baseline: 1.1454x; 1.1454x over previous
#include <cuda_runtime.h>

#define NV   2000000
#define NC   2000
#define NE   16000
#define NREP 8         // replicas per cluster, padded to 32B stride
#define GRID 296       // 2 CTAs/SM x 148 SMs: all blocks co-resident
#define TPB  256

// Scratch (no cudaMalloc allowed).
// Replica r of cluster c at float4 index c*16 + r*2 (32B apart: own L2 sector).
__device__ float4       g_rsum[NC * NREP * 2];   // 512 KB
__device__ unsigned int g_icnt[NC];
// Monotonic grid-barrier counters (never reset; grow by GRID per launch).
__device__ unsigned int g_bar0, g_bar1;

__device__ __forceinline__ void red_v4(float4* a, float x, float y, float z, float w) {
    asm volatile("red.global.add.v4.f32 [%0], {%1,%2,%3,%4};"
                 :: "l"(a), "f"(x), "f"(y), "f"(z), "f"(w) : "memory");
}
__device__ __forceinline__ void red_u32(unsigned int* a, unsigned int v) {
    asm volatile("red.global.add.u32 [%0], %1;" :: "l"(a), "r"(v) : "memory");
}
__device__ __forceinline__ unsigned long long pack2(float a, float b) {
    unsigned long long r;
    asm("mov.b64 %0, {%1, %2};" : "=l"(r) : "f"(a), "f"(b));
    return r;
}
__device__ __forceinline__ void unpack2(unsigned long long v, float& a, float& b) {
    asm("mov.b64 {%0, %1}, %2;" : "=f"(a), "=f"(b) : "l"(v));
}
__device__ __forceinline__ void ffma2(unsigned long long& d,
                                      unsigned long long a, unsigned long long b) {
    asm("fma.rn.f32x2 %0, %1, %2, %0;" : "+l"(d) : "l"(a), "l"(b));
}

// Software grid barrier: monotonic counter, wrap-free across graph replays.
// All GRID blocks are co-resident (2 CTAs/SM @ 72KB smem), so spinning is safe.
__device__ __forceinline__ void grid_barrier(unsigned int* ctr) {
    __syncthreads();
    if (threadIdx.x == 0) {
        __threadfence();
        unsigned int t = atomicAdd(ctr, 1u);
        unsigned int target = (t / GRID + 1u) * GRID;
        unsigned int v;
        do {
            asm volatile("ld.acquire.gpu.u32 %0, [%1];" : "=r"(v) : "l"(ctr));
        } while (v < target);
        __threadfence();
    }
    __syncthreads();
}

// ---------------------------------------------------------------------------
// ONE fused kernel, 296 x 256 (proven R10 shape).
// Phase 0: zero accumulators (512KB), preload W2, zero smem hist.
// Phase 1: segment sum — red.v4 to padded replicas (1 L2 request/voxel,
//          per-request LTS cost => minimal request count) + smem count hist.
//          Streaming reads use __ldcs so replica lines stay L2-resident.
// Phase 2: blocks 0..249 run the 64-edge MLP (FFMA2 Phase B).
// smem floats: W2 [0,8192) | h [8192,16384) | misc [16384,18432)
// ---------------------------------------------------------------------------
__global__ __launch_bounds__(TPB) void k_fused(const float* __restrict__ data,
                                               const int*   __restrict__ cid,
                                               const int*   __restrict__ eidx,
                                               const float* __restrict__ W1,
                                               const float* __restrict__ b1,
                                               const float* __restrict__ W2,
                                               const float* __restrict__ b2,
                                               float*       __restrict__ out) {
    extern __shared__ float sm[];
    float* s_W2   = sm;                      // 8192 floats [128][64]
    float* s_h    = sm + 8192;               // 8192 floats [128][64] k-major
    float* s_misc = sm + 16384;              // 2048 floats

    const int t   = threadIdx.x;
    const int bid = blockIdx.x;

    // ---- Phase 0 ----
    for (int i = bid * TPB + t; i < NC * NREP * 2; i += GRID * TPB)
        g_rsum[i] = make_float4(0.f, 0.f, 0.f, 0.f);
    for (int i = bid * TPB + t; i < NC; i += GRID * TPB)
        g_icnt[i] = 0u;
    for (int i = t; i < 8192 / 4; i += TPB)
        ((float4*)s_W2)[i] = ((const float4*)W2)[i];
    unsigned int* s_cnt = (unsigned int*)s_misc;   // 8KB histogram
    for (int i = t; i < NC; i += TPB) s_cnt[i] = 0u;

    grid_barrier(&g_bar0);

    // ---- Phase 1: segment sum ----
    {
        const int rep2 = ((bid * 8 + (t >> 5)) & (NREP - 1)) * 2;
        const int NG = NV / 4;
        const int stride = GRID * TPB;
#pragma unroll 2
        for (int g = bid * TPB + t; g < NG; g += stride) {
            const float4* p = (const float4*)data + (size_t)g * 5;
            float4 q0 = __ldcs(p + 0);
            float4 q1 = __ldcs(p + 1);
            float4 q2 = __ldcs(p + 2);
            float4 q3 = __ldcs(p + 3);
            float4 q4 = __ldcs(p + 4);
            int4 c = __ldcs((const int4*)cid + g);

            // voxel layout: [d f0 f1 f2 f3] x4 -> features are cols 1..4
            red_v4(&g_rsum[c.x * (NREP * 2) + rep2], q0.y, q0.z, q0.w, q1.x);
            red_v4(&g_rsum[c.y * (NREP * 2) + rep2], q1.z, q1.w, q2.x, q2.y);
            red_v4(&g_rsum[c.z * (NREP * 2) + rep2], q2.w, q3.x, q3.y, q3.z);
            red_v4(&g_rsum[c.w * (NREP * 2) + rep2], q4.x, q4.y, q4.z, q4.w);

            atomicAdd(&s_cnt[c.x], 1u);
            atomicAdd(&s_cnt[c.y], 1u);
            atomicAdd(&s_cnt[c.z], 1u);
            atomicAdd(&s_cnt[c.w], 1u);
        }
        __syncthreads();
        for (int i = t; i < NC; i += TPB) {
            unsigned int v = s_cnt[i];
            if (v) red_u32(&g_icnt[i], v);
        }
    }

    grid_barrier(&g_bar1);

    // ---- Phase 2: edge MLP on blocks 0..249 (64 edges each) ----
    if (bid >= NE / 64) return;

    float* s_W1   = s_misc;          // 512 floats [4][128]  (hist is dead)
    float* s_b1   = s_misc + 512;    // 128
    float* s_b2   = s_misc + 640;    // 64
    float* s_pool = s_misc + 704;    // 320 floats [64][5]

    __syncthreads();
    if (t < 128) ((float4*)s_W1)[t] = ((const float4*)W1)[t];
    if (t < 128) s_b1[t] = b1[t];
    if (t < 64)  s_b2[t] = b2[t];

    const int base = bid * 64;

    // Gather: 4 threads/edge, each sums 2 padded replicas of both endpoints
    // (4 pipelined LDG.128 from warm L2), 2-step shfl reduce.
    {
        int q = t & 3;
        int e = t >> 2;
        int eg = base + e;
        int a = __ldg(eidx + eg);
        int b = __ldg(eidx + NE + eg);

        const float4* ra = g_rsum + a * (NREP * 2) + q * 4;
        const float4* rb = g_rsum + b * (NREP * 2) + q * 4;
        float4 va0 = __ldg(ra + 0);
        float4 va1 = __ldg(ra + 2);
        float4 vb0 = __ldg(rb + 0);
        float4 vb1 = __ldg(rb + 2);
        float4 s = make_float4(va0.x + va1.x + vb0.x + vb1.x,
                               va0.y + va1.y + vb0.y + vb1.y,
                               va0.z + va1.z + vb0.z + vb1.z,
                               va0.w + va1.w + vb0.w + vb1.w);
#pragma unroll
        for (int off = 2; off > 0; off >>= 1) {
            s.x += __shfl_down_sync(0xffffffff, s.x, off);
            s.y += __shfl_down_sync(0xffffffff, s.y, off);
            s.z += __shfl_down_sync(0xffffffff, s.z, off);
            s.w += __shfl_down_sync(0xffffffff, s.w, off);
        }
        if (q == 0) {
            float cnt = (float)(__ldg(g_icnt + a) + __ldg(g_icnt + b));
            float inv = 1.f / fmaxf(cnt, 1.f);
            s_pool[e * 5 + 0] = s.x * inv;
            s_pool[e * 5 + 1] = s.y * inv;
            s_pool[e * 5 + 2] = s.z * inv;
            s_pool[e * 5 + 3] = s.w * inv;
        }
    }
    __syncthreads();

    // Phase A: e = t&63, k-group kq = (t>>6)*32.
    {
        int e  = t & 63;
        int kq = (t >> 6) * 32;
        float p0 = s_pool[e * 5 + 0];
        float p1 = s_pool[e * 5 + 1];
        float p2 = s_pool[e * 5 + 2];
        float p3 = s_pool[e * 5 + 3];
#pragma unroll 4
        for (int j = 0; j < 32; j++) {
            int k = kq + j;
            float h = s_b1[k]
                    + p0 * s_W1[0 * 128 + k]
                    + p1 * s_W1[1 * 128 + k]
                    + p2 * s_W1[2 * 128 + k]
                    + p3 * s_W1[3 * 128 + k];
            s_h[k * 64 + e] = fmaxf(h, 0.f);
        }
    }
    __syncthreads();

    // Phase B: 4 edges x 4 outs per thread, packed f32x2 accumulators.
    const int tx = t & 15;
    const int ty = t >> 4;
    unsigned long long acc[4][2];
#pragma unroll
    for (int i = 0; i < 4; i++) { acc[i][0] = 0ull; acc[i][1] = 0ull; }

    const float4* hf4 = (const float4*)s_h;    // [128][16]
    const float4* wf4 = (const float4*)s_W2;   // [128][16]
#pragma unroll 4
    for (int k = 0; k < 128; k++) {
        float4 w = wf4[k * 16 + tx];           // conflict-free
        float4 h = hf4[k * 16 + ty];           // broadcast
        unsigned long long w01 = pack2(w.x, w.y);
        unsigned long long w23 = pack2(w.z, w.w);
        float hv[4] = {h.x, h.y, h.z, h.w};
#pragma unroll
        for (int i = 0; i < 4; i++) {
            unsigned long long hh = pack2(hv[i], hv[i]);
            ffma2(acc[i][0], hh, w01);
            ffma2(acc[i][1], hh, w23);
        }
    }

    float c0 = s_b2[tx * 4 + 0];
    float c1 = s_b2[tx * 4 + 1];
    float c2 = s_b2[tx * 4 + 2];
    float c3 = s_b2[tx * 4 + 3];
#pragma unroll
    for (int i = 0; i < 4; i++) {
        int e = base + ty * 4 + i;
        float a0, a1, a2, a3;
        unpack2(acc[i][0], a0, a1);
        unpack2(acc[i][1], a2, a3);
        float4 o = make_float4(a0 + c0, a1 + c1, a2 + c2, a3 + c3);
        ((float4*)out)[e * 16 + tx] = o;
    }
}

// ---------------------------------------------------------------------------
// Launch: ONE kernel node (graph-capturable)
// ---------------------------------------------------------------------------
extern "C" void kernel_launch(void* const* d_in, const int* in_sizes, int n_in,
                              void* d_out, int out_size) {
    const float* data = (const float*)d_in[0];
    const int*   cid  = (const int*)  d_in[1];
    const int*   eidx = (const int*)  d_in[2];
    const float* W1   = (const float*)d_in[3];
    const float* b1   = (const float*)d_in[4];
    const float* W2   = (const float*)d_in[5];
    const float* b2   = (const float*)d_in[6];
    float*       out  = (float*)d_out;

    cudaFuncSetAttribute(k_fused, cudaFuncAttributeMaxDynamicSharedMemorySize, 73728);

    k_fused<<<GRID, TPB, 73728>>>(data, cid, eidx, W1, b1, W2, b2, out);
}

// round 15
// speedup vs baseline: 1.4822x; 1.2940x over previous
#include <cuda_runtime.h>

#define NV   2000000
#define NC   2000
#define NE   16000
#define NREP 8         // replicas per cluster, padded to 32B stride
#define GRID 296       // 2 CTAs/SM x 148 SMs: all blocks co-resident
#define TPB  256

// Scratch (no cudaMalloc allowed).
// Replica r of cluster c at float4 index c*16 + r*2 (32B apart: own L2 sector).
__device__ float4       g_rsum[NC * NREP * 2];   // 512 KB
__device__ unsigned int g_icnt[NC];
// Monotonic grid-barrier counters (never reset; grow by GRID per launch).
__device__ unsigned int g_bar0, g_bar1;

__device__ __forceinline__ void red_v4(float4* a, float x, float y, float z, float w) {
    asm volatile("red.global.add.v4.f32 [%0], {%1,%2,%3,%4};"
                 :: "l"(a), "f"(x), "f"(y), "f"(z), "f"(w) : "memory");
}
__device__ __forceinline__ void red_u32(unsigned int* a, unsigned int v) {
    asm volatile("red.global.add.u32 [%0], %1;" :: "l"(a), "r"(v) : "memory");
}
__device__ __forceinline__ unsigned long long pack2(float a, float b) {
    unsigned long long r;
    asm("mov.b64 %0, {%1, %2};" : "=l"(r) : "f"(a), "f"(b));
    return r;
}
__device__ __forceinline__ void unpack2(unsigned long long v, float& a, float& b) {
    asm("mov.b64 {%0, %1}, %2;" : "=f"(a), "=f"(b) : "l"(v));
}
__device__ __forceinline__ void ffma2(unsigned long long& d,
                                      unsigned long long a, unsigned long long b) {
    asm("fma.rn.f32x2 %0, %1, %2, %0;" : "+l"(d) : "l"(a), "l"(b));
}

// Software grid barrier: monotonic counter, wrap-free across graph replays.
// All GRID blocks are co-resident (2 CTAs/SM @ 72KB smem), so spinning is safe.
__device__ __forceinline__ void grid_barrier(unsigned int* ctr) {
    __syncthreads();
    if (threadIdx.x == 0) {
        __threadfence();
        unsigned int t = atomicAdd(ctr, 1u);
        unsigned int target = (t / GRID + 1u) * GRID;
        unsigned int v;
        do {
            asm volatile("ld.acquire.gpu.u32 %0, [%1];" : "=r"(v) : "l"(ctr));
        } while (v < target);
        __threadfence();
    }
    __syncthreads();
}

// ---------------------------------------------------------------------------
// ONE fused kernel, 296 x 256 (proven R10 shape).
// Phase 1 uses DEFAULT-policy loads (__ldg): the 48MB input fits in the
// 126MB L2 and stays resident across graph replays — the timed regime.
// (__ldcs evict-first destroyed that residency in R13: -8us wall.)
// smem floats: W2 [0,8192) | h [8192,16384) | misc [16384,18432)
// ---------------------------------------------------------------------------
__global__ __launch_bounds__(TPB) void k_fused(const float* __restrict__ data,
                                               const int*   __restrict__ cid,
                                               const int*   __restrict__ eidx,
                                               const float* __restrict__ W1,
                                               const float* __restrict__ b1,
                                               const float* __restrict__ W2,
                                               const float* __restrict__ b2,
                                               float*       __restrict__ out) {
    extern __shared__ float sm[];
    float* s_W2   = sm;                      // 8192 floats [128][64]
    float* s_h    = sm + 8192;               // 8192 floats [128][64] k-major
    float* s_misc = sm + 16384;              // 2048 floats

    const int t   = threadIdx.x;
    const int bid = blockIdx.x;

    // ---- Phase 0: zero accumulators; preload W2; zero smem hist ----
    for (int i = bid * TPB + t; i < NC * NREP * 2; i += GRID * TPB)
        g_rsum[i] = make_float4(0.f, 0.f, 0.f, 0.f);
    for (int i = bid * TPB + t; i < NC; i += GRID * TPB)
        g_icnt[i] = 0u;
    for (int i = t; i < 8192 / 4; i += TPB)
        ((float4*)s_W2)[i] = ((const float4*)W2)[i];
    unsigned int* s_cnt = (unsigned int*)s_misc;   // 8KB histogram
    for (int i = t; i < NC; i += TPB) s_cnt[i] = 0u;

    grid_barrier(&g_bar0);

    // ---- Phase 1: segment sum ----
    {
        const int rep2 = ((bid * 8 + (t >> 5)) & (NREP - 1)) * 2;
        const int NG = NV / 4;
        const int stride = GRID * TPB;
#pragma unroll 2
        for (int g = bid * TPB + t; g < NG; g += stride) {
            const float4* p = (const float4*)data + (size_t)g * 5;
            float4 q0 = __ldg(p + 0);
            float4 q1 = __ldg(p + 1);
            float4 q2 = __ldg(p + 2);
            float4 q3 = __ldg(p + 3);
            float4 q4 = __ldg(p + 4);
            int4 c = __ldg((const int4*)cid + g);

            // voxel layout: [d f0 f1 f2 f3] x4 -> features are cols 1..4
            red_v4(&g_rsum[c.x * (NREP * 2) + rep2], q0.y, q0.z, q0.w, q1.x);
            red_v4(&g_rsum[c.y * (NREP * 2) + rep2], q1.z, q1.w, q2.x, q2.y);
            red_v4(&g_rsum[c.z * (NREP * 2) + rep2], q2.w, q3.x, q3.y, q3.z);
            red_v4(&g_rsum[c.w * (NREP * 2) + rep2], q4.x, q4.y, q4.z, q4.w);

            atomicAdd(&s_cnt[c.x], 1u);
            atomicAdd(&s_cnt[c.y], 1u);
            atomicAdd(&s_cnt[c.z], 1u);
            atomicAdd(&s_cnt[c.w], 1u);
        }
        __syncthreads();
        for (int i = t; i < NC; i += TPB) {
            unsigned int v = s_cnt[i];
            if (v) red_u32(&g_icnt[i], v);
        }
    }

    grid_barrier(&g_bar1);

    // ---- Phase 2: edge MLP on blocks 0..249 (64 edges each) ----
    if (bid >= NE / 64) return;

    float* s_W1   = s_misc;          // 512 floats [4][128]  (hist is dead)
    float* s_b1   = s_misc + 512;    // 128
    float* s_b2   = s_misc + 640;    // 64
    float* s_pool = s_misc + 704;    // 320 floats [64][5]

    __syncthreads();
    if (t < 128) ((float4*)s_W1)[t] = ((const float4*)W1)[t];
    if (t < 128) s_b1[t] = b1[t];
    if (t < 64)  s_b2[t] = b2[t];

    const int base = bid * 64;

    // Gather: 4 threads/edge, each sums 2 padded replicas of both endpoints
    // (4 pipelined LDG.128 from warm L2), 2-step shfl reduce.
    {
        int q = t & 3;
        int e = t >> 2;
        int eg = base + e;
        int a = __ldg(eidx + eg);
        int b = __ldg(eidx + NE + eg);

        const float4* ra = g_rsum + a * (NREP * 2) + q * 4;
        const float4* rb = g_rsum + b * (NREP * 2) + q * 4;
        float4 va0 = __ldg(ra + 0);
        float4 va1 = __ldg(ra + 2);
        float4 vb0 = __ldg(rb + 0);
        float4 vb1 = __ldg(rb + 2);
        float4 s = make_float4(va0.x + va1.x + vb0.x + vb1.x,
                               va0.y + va1.y + vb0.y + vb1.y,
                               va0.z + va1.z + vb0.z + vb1.z,
                               va0.w + va1.w + vb0.w + vb1.w);
#pragma unroll
        for (int off = 2; off > 0; off >>= 1) {
            s.x += __shfl_down_sync(0xffffffff, s.x, off);
            s.y += __shfl_down_sync(0xffffffff, s.y, off);
            s.z += __shfl_down_sync(0xffffffff, s.z, off);
            s.w += __shfl_down_sync(0xffffffff, s.w, off);
        }
        if (q == 0) {
            float cnt = (float)(__ldg(g_icnt + a) + __ldg(g_icnt + b));
            float inv = 1.f / fmaxf(cnt, 1.f);
            s_pool[e * 5 + 0] = s.x * inv;
            s_pool[e * 5 + 1] = s.y * inv;
            s_pool[e * 5 + 2] = s.z * inv;
            s_pool[e * 5 + 3] = s.w * inv;
        }
    }
    __syncthreads();

    // Phase A: e = t&63, k-group kq = (t>>6)*32.
    {
        int e  = t & 63;
        int kq = (t >> 6) * 32;
        float p0 = s_pool[e * 5 + 0];
        float p1 = s_pool[e * 5 + 1];
        float p2 = s_pool[e * 5 + 2];
        float p3 = s_pool[e * 5 + 3];
#pragma unroll 4
        for (int j = 0; j < 32; j++) {
            int k = kq + j;
            float h = s_b1[k]
                    + p0 * s_W1[0 * 128 + k]
                    + p1 * s_W1[1 * 128 + k]
                    + p2 * s_W1[2 * 128 + k]
                    + p3 * s_W1[3 * 128 + k];
            s_h[k * 64 + e] = fmaxf(h, 0.f);
        }
    }
    __syncthreads();

    // Phase B: 4 edges x 4 outs per thread, packed f32x2 accumulators.
    const int tx = t & 15;
    const int ty = t >> 4;
    unsigned long long acc[4][2];
#pragma unroll
    for (int i = 0; i < 4; i++) { acc[i][0] = 0ull; acc[i][1] = 0ull; }

    const float4* hf4 = (const float4*)s_h;    // [128][16]
    const float4* wf4 = (const float4*)s_W2;   // [128][16]
#pragma unroll 4
    for (int k = 0; k < 128; k++) {
        float4 w = wf4[k * 16 + tx];           // conflict-free
        float4 h = hf4[k * 16 + ty];           // broadcast
        unsigned long long w01 = pack2(w.x, w.y);
        unsigned long long w23 = pack2(w.z, w.w);
        float hv[4] = {h.x, h.y, h.z, h.w};
#pragma unroll
        for (int i = 0; i < 4; i++) {
            unsigned long long hh = pack2(hv[i], hv[i]);
            ffma2(acc[i][0], hh, w01);
            ffma2(acc[i][1], hh, w23);
        }
    }

    float c0 = s_b2[tx * 4 + 0];
    float c1 = s_b2[tx * 4 + 1];
    float c2 = s_b2[tx * 4 + 2];
    float c3 = s_b2[tx * 4 + 3];
#pragma unroll
    for (int i = 0; i < 4; i++) {
        int e = base + ty * 4 + i;
        float a0, a1, a2, a3;
        unpack2(acc[i][0], a0, a1);
        unpack2(acc[i][1], a2, a3);
        float4 o = make_float4(a0 + c0, a1 + c1, a2 + c2, a3 + c3);
        ((float4*)out)[e * 16 + tx] = o;
    }
}

// ---------------------------------------------------------------------------
// Launch: ONE kernel node (graph-capturable)
// ---------------------------------------------------------------------------
extern "C" void kernel_launch(void* const* d_in, const int* in_sizes, int n_in,
                              void* d_out, int out_size) {
    const float* data = (const float*)d_in[0];
    const int*   cid  = (const int*)  d_in[1];
    const int*   eidx = (const int*)  d_in[2];
    const float* W1   = (const float*)d_in[3];
    const float* b1   = (const float*)d_in[4];
    const float* W2   = (const float*)d_in[5];
    const float* b2   = (const float*)d_in[6];
    float*       out  = (float*)d_out;

    cudaFuncSetAttribute(k_fused, cudaFuncAttributeMaxDynamicSharedMemorySize, 73728);

    k_fused<<<GRID, TPB, 73728>>>(data, cid, eidx, W1, b1, W2, b2, out);
}